// round 5
// baseline (speedup 1.0000x reference)
#include <cuda_runtime.h>
#include <cstdint>

#define BATCH 4096

// ---------------- Device scratch ----------------
__device__ unsigned g_w1p[20];                          // 25 sign bits per filter
__device__ __align__(16) signed char g_w2i8[5*64*144];  // B: [ky][f(64)][j(144)] int8 +-1, pad 0
__device__ __align__(16) unsigned g_w3p[1024*80];       // per out-neuron: 2450 bits (order pix*50+c), pad 80
__device__ unsigned g_w4p[10*32];                       // per out-neuron: 1024 sign bits
__device__ unsigned g_xrow[BATCH*64];                   // per image: [0..31]=mask rows, [32..63]=sign rows
__device__ __align__(16) unsigned char g_a1[BATCH*6480];// conv1 out: padded 18x18x20 bytes {0,1}, channel-last
__device__ __align__(16) unsigned g_packed2[BATCH*80];  // fc3 input bits (order pix*50+c), padded
__device__ unsigned g_packed3[BATCH*32];                // fc4 input bits (1024)

// ---------------- Weight packing ----------------
// ranges: [0,20) w1 | [20,46100) w2i8 | [46100,128020) w3 | [128020,128340) w4
__global__ void pack_w_kernel(const float* __restrict__ w1, const float* __restrict__ w2,
                              const float* __restrict__ w3, const float* __restrict__ w4) {
    int id = blockIdx.x * blockDim.x + threadIdx.x;
    if (id < 20) {
        unsigned m = 0;
        #pragma unroll
        for (int t = 0; t < 25; t++) m |= (unsigned)(w1[id*25 + t] > 0.0f) << t;
        g_w1p[id] = m;
    } else if (id < 46100) {
        int idx = id - 20;
        int ky = idx / 9216, r2 = idx % 9216;
        int f = r2 / 144, j = r2 % 144;
        signed char v = 0;
        if (j < 100 && f < 50) {
            int c = j % 20, kx = j / 20;
            v = (w2[f*500 + c*25 + ky*5 + kx] > 0.0f) ? 1 : -1;
        }
        g_w2i8[idx] = v;
    } else if (id < 128020) {
        int idx = id - 46100; int o = idx / 80, w = idx % 80;
        unsigned m = 0;
        for (int k = 0; k < 32; k++) {
            int j = w*32 + k;
            if (j < 2450) {
                int pix = j / 50, c = j % 50;  // orig flat index = c*49 + pix
                m |= (unsigned)(w3[o*2450 + c*49 + pix] > 0.0f) << k;
            }
        }
        g_w3p[idx] = m;
    } else if (id < 128340) {
        int idx = id - 128020; int o = idx / 32, w = idx % 32;
        unsigned m = 0;
        #pragma unroll
        for (int k = 0; k < 32; k++) m |= (unsigned)(w4[o*1024 + w*32 + k] > 0.0f) << k;
        g_w4p[idx] = m;
    }
}

// ---------------- pack x into per-row mask/sign bit words ----------------
__global__ void pack_xrow_kernel(const float* __restrict__ x) {
    int id = blockIdx.x * 128 + threadIdx.x;          // 1024*128 = 4096*32
    int b = id >> 5, r = id & 31;
    unsigned m = 0, p = 0;
    if (r >= 2 && r < 30) {
        const float* row = x + b*784 + (r-2)*28;
        #pragma unroll
        for (int xx = 0; xx < 28; xx++) {
            float v = row[xx];
            m |= (unsigned)(v != 0.0f) << (xx + 2);
            p |= (unsigned)(v > 0.0f)  << (xx + 2);
        }
    }
    g_xrow[b*64 + r]      = m;
    g_xrow[b*64 + 32 + r] = p;
}

// ---------------- conv1 + relu + maxpool2 + sign -> channel-last bytes (padded 18x18x20) ----------------
__global__ void __launch_bounds__(128) conv1_kernel(const float* __restrict__ b1) {
    __shared__ unsigned w1s[20];
    __shared__ float b1s[20];
    int tid = threadIdx.x;
    if (tid < 20) { w1s[tid] = g_w1p[tid]; b1s[tid] = b1[tid]; }
    __syncthreads();

    int id = blockIdx.x * 128 + tid;                 // 6272*128 = 4096*196
    int b = id / 196, pix = id % 196;
    int py = pix / 14, px = pix % 14;
    unsigned char* a1b = g_a1 + b * 6480;

    // zero the 128 border pixels (threads pix<128)
    if (pix < 128) {
        int y, xx;
        if (pix < 72) { int ry = pix / 18; y = (ry < 2) ? ry : ry + 14; xx = pix % 18; }
        else { int j = pix - 72; int cx = j % 4; xx = (cx < 2) ? cx : cx + 14; y = 2 + j / 4; }
        unsigned* d = (unsigned*)(a1b + (y*18 + xx)*20);
        #pragma unroll
        for (int q = 0; q < 5; q++) d[q] = 0u;
    }

    const unsigned* xr = g_xrow + b*64;
    unsigned mr[6], pr[6];
    #pragma unroll
    for (int i = 0; i < 6; i++) { mr[i] = xr[2*py + i]; pr[i] = xr[32 + 2*py + i]; }

    unsigned M[4], P[4]; int pm[4];
    #pragma unroll
    for (int dy = 0; dy < 2; dy++)
    #pragma unroll
    for (int dx = 0; dx < 2; dx++) {
        int sh = 2*px + dx;
        unsigned m = 0, p = 0;
        #pragma unroll
        for (int ky = 0; ky < 5; ky++) {
            m |= ((mr[dy + ky] >> sh) & 31u) << (5*ky);
            p |= ((pr[dy + ky] >> sh) & 31u) << (5*ky);
        }
        int w = dy*2 + dx;
        M[w] = m; P[w] = p; pm[w] = __popc(m);
    }

    unsigned word = 0;
    #pragma unroll
    for (int c = 0; c < 20; c++) {
        unsigned wp = w1s[c];
        int d0 = 2*__popc(M[0] & ~(P[0] ^ wp)) - pm[0];
        int d1 = 2*__popc(M[1] & ~(P[1] ^ wp)) - pm[1];
        int d2 = 2*__popc(M[2] & ~(P[2] ^ wp)) - pm[2];
        int d3 = 2*__popc(M[3] & ~(P[3] ^ wp)) - pm[3];
        int mx = max(max(d0, d1), max(d2, d3));
        if ((float)mx + b1s[c] > 0.0f) word |= 1u << c;
    }

    // expand 20 bits -> 20 bytes {0,1} at padded (py+2, px+2)
    unsigned* dst = (unsigned*)(a1b + ((py+2)*18 + (px+2))*20);
    #pragma unroll
    for (int q = 0; q < 5; q++) {
        unsigned u = ((word >> (4*q)) & 1u)
                   | (((word >> (4*q+1)) & 1u) << 8)
                   | (((word >> (4*q+2)) & 1u) << 16)
                   | (((word >> (4*q+3)) & 1u) << 24);
        dst[q] = u;
    }
}

// ---------------- conv2 via int8 mma.sync implicit GEMM; one image per CTA ----------------
// smem layout (bytes):
#define OFF_IMG  0            // 6480  (18*18*20)
#define OFF_B    6496         // 46080 (5*64*144)
#define OFF_BIAS 52576        // 256   (64 floats)
#define OFF_PACK 52832        // 320   (80 u32)
#define OFF_A    53152        // 29952 (208*144)
#define OFF_V    83104        // 26624 (208*64 i16)
#define SMEM_SZ  109728

__device__ __forceinline__ void mma_s8(int* d, unsigned a0, unsigned a1, unsigned a2, unsigned a3,
                                       unsigned b0, unsigned b1) {
    asm volatile("mma.sync.aligned.m16n8k32.row.col.s32.s8.s8.s32 "
                 "{%0,%1,%2,%3},{%4,%5,%6,%7},{%8,%9},{%0,%1,%2,%3};"
                 : "+r"(d[0]), "+r"(d[1]), "+r"(d[2]), "+r"(d[3])
                 : "r"(a0), "r"(a1), "r"(a2), "r"(a3), "r"(b0), "r"(b1));
}

__global__ void __launch_bounds__(256) conv2_mma_kernel(const float* __restrict__ b2) {
    extern __shared__ __align__(16) unsigned char smem[];
    int tid = threadIdx.x;
    int b = blockIdx.x;
    int wid = tid >> 5, lane = tid & 31;
    int gr = lane >> 2, tig = lane & 3;

    // stage image (405 uint4), B weights (2880 uint4), bias, zero packrow
    {
        const uint4* s = (const uint4*)(g_a1 + b*6480);
        uint4* d = (uint4*)(smem + OFF_IMG);
        for (int t = tid; t < 405; t += 256) d[t] = s[t];
        const uint4* ws = (const uint4*)g_w2i8;
        uint4* wd = (uint4*)(smem + OFF_B);
        for (int t = tid; t < 2880; t += 256) wd[t] = ws[t];
        float* bs = (float*)(smem + OFF_BIAS);
        if (tid < 64) bs[tid] = (tid < 50) ? b2[tid] : 0.0f;
        if (tid < 80) ((unsigned*)(smem + OFF_PACK))[tid] = 0u;
    }
    __syncthreads();

    int mt0 = wid, mt1 = wid + 8;
    bool has1 = (mt1 < 13);
    int acc[2][8][4];
    #pragma unroll
    for (int m = 0; m < 2; m++)
        #pragma unroll
        for (int n = 0; n < 8; n++)
            #pragma unroll
            for (int k = 0; k < 4; k++) acc[m][n][k] = 0;

    for (int ky = 0; ky < 5; ky++) {
        // build A chunk [208 x 128] (rows >=196 left as-is; unused)
        if (tid < 196) {
            int py = tid / 14, px = tid % 14;
            const unsigned* src = (const unsigned*)(smem + OFF_IMG + ((py + ky)*18 + px)*20);
            unsigned* dst = (unsigned*)(smem + OFF_A + tid*144);
            #pragma unroll
            for (int j = 0; j < 25; j++) dst[j] = src[j];
            #pragma unroll
            for (int j = 25; j < 32; j++) dst[j] = 0u;
        }
        __syncthreads();

        const unsigned char* As = smem + OFF_A;
        const unsigned char* Bs = smem + OFF_B + ky*9216;
        #pragma unroll
        for (int ks = 0; ks < 4; ks++) {
            int kb = ks*32 + 4*tig;
            unsigned a0[2], a1v[2], a2[2], a3[2];
            {
                int r = mt0*16 + gr;
                a0[0]  = *(const unsigned*)(As + r*144 + kb);
                a1v[0] = *(const unsigned*)(As + (r+8)*144 + kb);
                a2[0]  = *(const unsigned*)(As + r*144 + kb + 16);
                a3[0]  = *(const unsigned*)(As + (r+8)*144 + kb + 16);
            }
            if (has1) {
                int r = mt1*16 + gr;
                a0[1]  = *(const unsigned*)(As + r*144 + kb);
                a1v[1] = *(const unsigned*)(As + (r+8)*144 + kb);
                a2[1]  = *(const unsigned*)(As + r*144 + kb + 16);
                a3[1]  = *(const unsigned*)(As + (r+8)*144 + kb + 16);
            }
            #pragma unroll
            for (int nt = 0; nt < 8; nt++) {
                int f = nt*8 + gr;
                unsigned b0 = *(const unsigned*)(Bs + f*144 + kb);
                unsigned b1 = *(const unsigned*)(Bs + f*144 + kb + 16);
                mma_s8(acc[0][nt], a0[0], a1v[0], a2[0], a3[0], b0, b1);
                if (has1) mma_s8(acc[1][nt], a0[1], a1v[1], a2[1], a3[1], b0, b1);
            }
        }
        __syncthreads();
    }

    // dump conv values to V (int16 [208][64])
    {
        unsigned* V = (unsigned*)(smem + OFF_V);  // as u32 pairs: row stride 32 u32
        #pragma unroll
        for (int mt = 0; mt < 2; mt++) {
            if (mt == 1 && !has1) break;
            int mb = (mt == 0 ? mt0 : mt1) * 16;
            #pragma unroll
            for (int nt = 0; nt < 8; nt++) {
                int n = nt*8 + 2*tig;
                int m = mb + gr;
                V[m*32 + (n >> 1)] = ((unsigned)acc[mt][nt][0] & 0xffffu) | ((unsigned)acc[mt][nt][1] << 16);
                V[(m+8)*32 + (n >> 1)] = ((unsigned)acc[mt][nt][2] & 0xffffu) | ((unsigned)acc[mt][nt][3] << 16);
            }
        }
    }
    __syncthreads();

    // pooling + bias + sign -> pack bits (bit index pix*50 + f)
    {
        const short* V = (const short*)(smem + OFF_V);
        const float* bs = (const float*)(smem + OFF_BIAS);
        unsigned* pack = (unsigned*)(smem + OFF_PACK);
        for (int it = tid; it < 2450; it += 256) {
            int pp = it / 50, f = it % 50;
            int y = pp / 7, x = pp % 7;
            int m00 = (2*y)*14 + 2*x;
            int v0 = V[m00*64 + f];
            int v1 = V[(m00+1)*64 + f];
            int v2 = V[(m00+14)*64 + f];
            int v3 = V[(m00+15)*64 + f];
            int mx = max(max(v0, v1), max(v2, v3));
            if ((float)mx + bs[f] > 0.0f) {
                int bi = pp*50 + f;
                atomicOr(&pack[bi >> 5], 1u << (bi & 31));
            }
        }
    }
    __syncthreads();
    if (tid < 20)
        ((uint4*)(g_packed2 + b*80))[tid] = ((const uint4*)(smem + OFF_PACK))[tid];
}

// ---------------- fc3: register-tiled 4 outputs x 8 batches per thread ----------------
__global__ void __launch_bounds__(128) fc3_kernel(const float* __restrict__ b3) {
    __shared__ __align__(16) unsigned sa[8*80];
    __shared__ int sna[8];
    int tid = threadIdx.x;
    int b0 = blockIdx.y * 8;
    for (int t = tid; t < 160; t += 128)
        ((uint4*)sa)[t] = ((const uint4*)(g_packed2 + b0*80))[t];
    __syncthreads();
    if (tid < 8) {
        int s = 0;
        #pragma unroll 8
        for (int i = 0; i < 80; i++) s += __popc(sa[tid*80 + i]);
        sna[tid] = s;
    }
    __syncthreads();

    int obase = blockIdx.x * 512 + tid;
    const uint4* wr0 = (const uint4*)(g_w3p + (obase      )*80);
    const uint4* wr1 = (const uint4*)(g_w3p + (obase + 128)*80);
    const uint4* wr2 = (const uint4*)(g_w3p + (obase + 256)*80);
    const uint4* wr3 = (const uint4*)(g_w3p + (obase + 384)*80);

    int cnt[4][8];
    #pragma unroll
    for (int j = 0; j < 4; j++)
        #pragma unroll
        for (int bb = 0; bb < 8; bb++) cnt[j][bb] = 0;

    #pragma unroll 2
    for (int i = 0; i < 20; i++) {
        uint4 w[4] = {wr0[i], wr1[i], wr2[i], wr3[i]};
        #pragma unroll
        for (int bb = 0; bb < 8; bb++) {
            uint4 a = *(const uint4*)&sa[bb*80 + i*4];
            #pragma unroll
            for (int j = 0; j < 4; j++) {
                cnt[j][bb] += __popc(a.x & w[j].x) + __popc(a.y & w[j].y)
                            + __popc(a.z & w[j].z) + __popc(a.w & w[j].w);
            }
        }
    }

    #pragma unroll
    for (int j = 0; j < 4; j++) {
        int o = obase + 128*j;
        float bias = b3[o];
        int widx = o >> 5;
        #pragma unroll
        for (int bb = 0; bb < 8; bb++) {
            float val = (float)(2*cnt[j][bb] - sna[bb]) + bias;
            unsigned word = __ballot_sync(0xffffffffu, val > 0.0f);
            if ((tid & 31) == 0) g_packed3[(b0 + bb)*32 + widx] = word;
        }
    }
}

// ---------------- fc4 ----------------
__global__ void __launch_bounds__(128) fc4_kernel(const float* __restrict__ b4, float* __restrict__ out) {
    __shared__ unsigned w4s[10*32];
    __shared__ float b4s[10];
    int tid = threadIdx.x;
    for (int t = tid; t < 320; t += 128) w4s[t] = g_w4p[t];
    if (tid < 10) b4s[tid] = b4[tid];
    __syncthreads();

    int b = blockIdx.x * 128 + tid;
    unsigned a[32]; int na = 0;
    #pragma unroll
    for (int i = 0; i < 32; i++) { a[i] = g_packed3[b*32 + i]; na += __popc(a[i]); }
    #pragma unroll
    for (int k = 0; k < 10; k++) {
        int cnt = 0;
        #pragma unroll
        for (int i = 0; i < 32; i++) cnt += __popc(a[i] & w4s[k*32 + i]);
        out[b*10 + k] = (float)(2*cnt - na) + b4s[k];
    }
}

// ---------------- launch ----------------
extern "C" void kernel_launch(void* const* d_in, const int* in_sizes, int n_in,
                              void* d_out, int out_size) {
    const float* x  = (const float*)d_in[0];
    const float* w1 = (const float*)d_in[1];
    const float* b1 = (const float*)d_in[2];
    const float* w2 = (const float*)d_in[3];
    const float* b2 = (const float*)d_in[4];
    const float* w3 = (const float*)d_in[5];
    const float* b3 = (const float*)d_in[6];
    const float* w4 = (const float*)d_in[7];
    const float* b4 = (const float*)d_in[8];
    float* out = (float*)d_out;

    static bool attr_set = false;
    if (!attr_set) {
        cudaFuncSetAttribute(conv2_mma_kernel, cudaFuncAttributeMaxDynamicSharedMemorySize, SMEM_SZ);
        attr_set = true;
    }

    pack_w_kernel<<<1003, 128>>>(w1, w2, w3, w4);    // 128340 items
    pack_xrow_kernel<<<1024, 128>>>(x);              // 4096*32 rows
    conv1_kernel<<<6272, 128>>>(b1);                 // 4096*196
    conv2_mma_kernel<<<4096, 256, SMEM_SZ>>>(b2);    // one image per CTA
    fc3_kernel<<<dim3(2, 512), 128>>>(b3);           // 1024 outs x (4096/8)
    fc4_kernel<<<32, 128>>>(b4, out);                // 4096
}

// round 7
// speedup vs baseline: 1.2395x; 1.2395x over previous
#include <cuda_runtime.h>

#define BATCH 4096

// ---------------- Device scratch ----------------
__device__ unsigned g_w1p[20];                         // 25 sign bits per filter
__device__ __align__(16) unsigned g_w2q[50*16];        // per filter: 500-bit window layout (p = t*20+c)
__device__ __align__(16) unsigned g_w3p[1024*80];      // per out-neuron: 2450 bits, order j' = pix*50+c, pad 80
__device__ unsigned g_w4p[10*32];                      // per out-neuron: 1024 sign bits
__device__ unsigned g_xrow[BATCH*64];                  // per image: [0..31]=mask rows, [32..63]=sign rows (bit xx+2)
__device__ unsigned g_packed1[BATCH*196];              // conv2 input: 20 ch bits per 14x14 pixel
__device__ __align__(16) unsigned g_packed2[BATCH*80]; // fc3 input bits (order pix*50+c), padded
__device__ unsigned g_packed3[BATCH*32];               // fc4 input bits (1024)

// ---------------- Weight packing ----------------
// ranges: [0,20) w1 | [20,820) w2q | [820,82740) w3 | [82740,83060) w4
__global__ void pack_w_kernel(const float* __restrict__ w1, const float* __restrict__ w2,
                              const float* __restrict__ w3, const float* __restrict__ w4) {
    int id = blockIdx.x * blockDim.x + threadIdx.x;
    if (id < 20) {
        unsigned m = 0;
        #pragma unroll
        for (int t = 0; t < 25; t++) m |= (unsigned)(w1[id*25 + t] > 0.0f) << t;
        g_w1p[id] = m;
    } else if (id < 820) {
        int idx = id - 20; int f = idx / 16, w = idx % 16;
        unsigned m = 0;
        for (int k = 0; k < 32; k++) {
            int p = w*32 + k;
            if (p < 500) {
                int t = p / 20, c = p % 20;
                m |= (unsigned)(w2[f*500 + c*25 + t] > 0.0f) << k;
            }
        }
        g_w2q[idx] = m;
    } else if (id < 82740) {
        int idx = id - 820; int o = idx / 80, w = idx % 80;
        unsigned m = 0;
        for (int k = 0; k < 32; k++) {
            int j = w*32 + k;
            if (j < 2450) {
                int pix = j / 50, c = j % 50;  // orig flat index = c*49 + pix
                m |= (unsigned)(w3[o*2450 + c*49 + pix] > 0.0f) << k;
            }
        }
        g_w3p[idx] = m;
    } else if (id < 83060) {
        int idx = id - 82740; int o = idx / 32, w = idx % 32;
        unsigned m = 0;
        #pragma unroll
        for (int k = 0; k < 32; k++) m |= (unsigned)(w4[o*1024 + w*32 + k] > 0.0f) << k;
        g_w4p[idx] = m;
    }
}

// ---------------- pack x into per-row mask/sign bit words ----------------
__global__ void pack_xrow_kernel(const float* __restrict__ x) {
    int id = blockIdx.x * 128 + threadIdx.x;          // 1024*128 = 4096*32
    int b = id >> 5, r = id & 31;
    unsigned m = 0, p = 0;
    if (r >= 2 && r < 30) {
        const float* row = x + b*784 + (r-2)*28;
        #pragma unroll
        for (int xx = 0; xx < 28; xx++) {
            float v = row[xx];
            m |= (unsigned)(v != 0.0f) << (xx + 2);
            p |= (unsigned)(v > 0.0f)  << (xx + 2);
        }
    }
    g_xrow[b*64 + r]      = m;
    g_xrow[b*64 + 32 + r] = p;
}

// ---------------- conv1 + relu + maxpool2 + sign -> packed channel bits ----------------
__global__ void __launch_bounds__(128) conv1_kernel(const float* __restrict__ b1) {
    __shared__ unsigned w1s[20];
    __shared__ float b1s[20];
    int tid = threadIdx.x;
    if (tid < 20) { w1s[tid] = g_w1p[tid]; b1s[tid] = b1[tid]; }
    __syncthreads();

    int id = blockIdx.x * 128 + tid;                 // 6272*128 = 4096*196
    if (id < BATCH*80) g_packed2[id] = 0;            // zero fc3-input rows for conv2's atomicOr
    int b = id / 196, pix = id % 196;
    int py = pix / 14, px = pix % 14;
    const unsigned* xr = g_xrow + b*64;

    unsigned mr[6], pr[6];
    #pragma unroll
    for (int i = 0; i < 6; i++) { mr[i] = xr[2*py + i]; pr[i] = xr[32 + 2*py + i]; }

    unsigned M[4], P[4]; int pm[4];
    #pragma unroll
    for (int dy = 0; dy < 2; dy++)
    #pragma unroll
    for (int dx = 0; dx < 2; dx++) {
        int sh = 2*px + dx;
        unsigned m = 0, p = 0;
        #pragma unroll
        for (int ky = 0; ky < 5; ky++) {
            m |= ((mr[dy + ky] >> sh) & 31u) << (5*ky);
            p |= ((pr[dy + ky] >> sh) & 31u) << (5*ky);
        }
        int w = dy*2 + dx;
        M[w] = m; P[w] = p; pm[w] = __popc(m);
    }

    unsigned word = 0;
    #pragma unroll
    for (int c = 0; c < 20; c++) {
        unsigned wp = w1s[c];
        int d0 = 2*__popc(M[0] & ~(P[0] ^ wp)) - pm[0];
        int d1 = 2*__popc(M[1] & ~(P[1] ^ wp)) - pm[1];
        int d2 = 2*__popc(M[2] & ~(P[2] ^ wp)) - pm[2];
        int d3 = 2*__popc(M[3] & ~(P[3] ^ wp)) - pm[3];
        int mx = max(max(d0, d1), max(d2, d3));
        if ((float)mx + b1s[c] > 0.0f) word |= 1u << c;
    }
    g_packed1[id] = word;
}

// ---------------- conv2: 2 passes of 2 windows; integer-threshold hit bits ----------------
__global__ void __launch_bounds__(128) conv2_kernel(const float* __restrict__ b2) {
    __shared__ __align__(16) unsigned sw[50*16];
    __shared__ int thr[50];
    int tid = threadIdx.x;
    for (int t = tid; t < 800; t += 128) sw[t] = g_w2q[t];
    // (float)d + bias > 0  <=>  d >= floor(-bias)+1   (d integer)
    if (tid < 50) thr[tid] = (int)floorf(-b2[tid]) + 1;
    __syncthreads();

    int id = blockIdx.x * 128 + tid;                 // 1568*128 = 4096*49
    int b = id / 49, pix = id % 49;
    int py = pix / 7, px = pix % 7;
    const unsigned* inb = g_packed1 + b * 196;

    unsigned long long bits = 0ull;

    #pragma unroll
    for (int dy = 0; dy < 2; dy++) {
        // load 5 rows x 6 cols for this pass (L1-resident)
        unsigned iw[30];
        #pragma unroll
        for (int i = 0; i < 5; i++) {
            int y = py*2 - 2 + dy + i;
            #pragma unroll
            for (int j = 0; j < 6; j++) {
                int xx = px*2 - 2 + j;
                unsigned v = 0u;
                if ((unsigned)y < 14u && (unsigned)xx < 14u) v = inb[y*14 + xx];
                iw[i*6+j] = v;
            }
        }

        // pack both x-windows (cols 0-4 and 1-5) into dense 500-bit layouts
        unsigned W0[16], W1[16];
        {
            unsigned long long a0 = 0, a1 = 0; int off = 0, wi = 0;
            #pragma unroll
            for (int ky = 0; ky < 5; ky++)
            #pragma unroll
            for (int kx = 0; kx < 5; kx++) {
                a0 |= (unsigned long long)iw[ky*6+kx]   << off;
                a1 |= (unsigned long long)iw[ky*6+kx+1] << off;
                off += 20;
                if (off >= 32) {
                    W0[wi] = (unsigned)a0; W1[wi] = (unsigned)a1; wi++;
                    a0 >>= 32; a1 >>= 32; off -= 32;
                }
            }
            W0[wi] = (unsigned)a0; W1[wi] = (unsigned)a1;
        }

        int S0 = 0, S1 = 0;
        #pragma unroll
        for (int j = 0; j < 16; j++) { S0 += __popc(W0[j]); S1 += __popc(W1[j]); }

        for (int f = 0; f < 50; f++) {
            const uint4* fp = (const uint4*)&sw[f*16];
            int P0 = 0, P1 = 0;
            #pragma unroll
            for (int q = 0; q < 4; q++) {
                uint4 w = fp[q];
                P0 += __popc(W0[q*4+0] & w.x) + __popc(W0[q*4+1] & w.y)
                    + __popc(W0[q*4+2] & w.z) + __popc(W0[q*4+3] & w.w);
                P1 += __popc(W1[q*4+0] & w.x) + __popc(W1[q*4+1] & w.y)
                    + __popc(W1[q*4+2] & w.z) + __popc(W1[q*4+3] & w.w);
            }
            int t = thr[f];
            unsigned hit = (unsigned)((2*P0 - S0 >= t) | (2*P1 - S1 >= t));
            bits |= (unsigned long long)hit << f;
        }
    }

    // scatter 50 bits into the fc3 bit row at offset pix*50
    unsigned* row = g_packed2 + b * 80;
    int base = pix * 50;
    int w0 = base >> 5, sh = base & 31;
    unsigned long long lo = bits << sh;
    atomicOr(&row[w0],     (unsigned)lo);
    atomicOr(&row[w0 + 1], (unsigned)(lo >> 32));
    if (sh >= 15) atomicOr(&row[w0 + 2], (unsigned)(bits >> (64 - sh)));
}

// ---------------- fc3: register-tiled 4 outputs x 8 batches per thread ----------------
__global__ void __launch_bounds__(128) fc3_kernel(const float* __restrict__ b3) {
    __shared__ __align__(16) unsigned sa[8*80];
    __shared__ int sna[8];
    int tid = threadIdx.x;
    int b0 = blockIdx.y * 8;
    for (int t = tid; t < 160; t += 128)
        ((uint4*)sa)[t] = ((const uint4*)(g_packed2 + b0*80))[t];
    __syncthreads();
    if (tid < 8) {
        int s = 0;
        #pragma unroll 8
        for (int i = 0; i < 80; i++) s += __popc(sa[tid*80 + i]);
        sna[tid] = s;
    }
    __syncthreads();

    int obase = blockIdx.x * 512 + tid;              // outputs obase + 128*j, j=0..3
    const uint4* wr0 = (const uint4*)(g_w3p + (obase      )*80);
    const uint4* wr1 = (const uint4*)(g_w3p + (obase + 128)*80);
    const uint4* wr2 = (const uint4*)(g_w3p + (obase + 256)*80);
    const uint4* wr3 = (const uint4*)(g_w3p + (obase + 384)*80);

    int cnt[4][8];
    #pragma unroll
    for (int j = 0; j < 4; j++)
        #pragma unroll
        for (int bb = 0; bb < 8; bb++) cnt[j][bb] = 0;

    #pragma unroll 2
    for (int i = 0; i < 20; i++) {
        uint4 w[4] = {wr0[i], wr1[i], wr2[i], wr3[i]};
        #pragma unroll
        for (int bb = 0; bb < 8; bb++) {
            uint4 a = *(const uint4*)&sa[bb*80 + i*4];
            #pragma unroll
            for (int j = 0; j < 4; j++) {
                cnt[j][bb] += __popc(a.x & w[j].x) + __popc(a.y & w[j].y)
                            + __popc(a.z & w[j].z) + __popc(a.w & w[j].w);
            }
        }
    }

    #pragma unroll
    for (int j = 0; j < 4; j++) {
        int o = obase + 128*j;
        float bias = b3[o];
        int widx = o >> 5;
        #pragma unroll
        for (int bb = 0; bb < 8; bb++) {
            float val = (float)(2*cnt[j][bb] - sna[bb]) + bias;
            unsigned word = __ballot_sync(0xffffffffu, val > 0.0f);
            if ((tid & 31) == 0) g_packed3[(b0 + bb)*32 + widx] = word;
        }
    }
}

// ---------------- fc4: [4096,1024] x [10,1024]^T -> float out ----------------
__global__ void __launch_bounds__(128) fc4_kernel(const float* __restrict__ b4, float* __restrict__ out) {
    __shared__ unsigned w4s[10*32];
    __shared__ float b4s[10];
    int tid = threadIdx.x;
    for (int t = tid; t < 320; t += 128) w4s[t] = g_w4p[t];
    if (tid < 10) b4s[tid] = b4[tid];
    __syncthreads();

    int b = blockIdx.x * 128 + tid;                  // 32*128 = 4096
    unsigned a[32]; int na = 0;
    #pragma unroll
    for (int i = 0; i < 32; i++) { a[i] = g_packed3[b*32 + i]; na += __popc(a[i]); }
    #pragma unroll
    for (int k = 0; k < 10; k++) {
        int cnt = 0;
        #pragma unroll
        for (int i = 0; i < 32; i++) cnt += __popc(a[i] & w4s[k*32 + i]);
        out[b*10 + k] = (float)(2*cnt - na) + b4s[k];
    }
}

// ---------------- launch ----------------
extern "C" void kernel_launch(void* const* d_in, const int* in_sizes, int n_in,
                              void* d_out, int out_size) {
    const float* x  = (const float*)d_in[0];
    const float* w1 = (const float*)d_in[1];
    const float* b1 = (const float*)d_in[2];
    const float* w2 = (const float*)d_in[3];
    const float* b2 = (const float*)d_in[4];
    const float* w3 = (const float*)d_in[5];
    const float* b3 = (const float*)d_in[6];
    const float* w4 = (const float*)d_in[7];
    const float* b4 = (const float*)d_in[8];
    float* out = (float*)d_out;

    pack_w_kernel<<<649, 128>>>(w1, w2, w3, w4);     // 83060 items
    pack_xrow_kernel<<<1024, 128>>>(x);              // 4096*32 rows
    conv1_kernel<<<6272, 128>>>(b1);                 // 4096*196 (+ zeroes g_packed2)
    conv2_kernel<<<1568, 128>>>(b2);                 // 4096*49
    fc3_kernel<<<dim3(2, 512), 128>>>(b3);           // 1024 outs x (4096/8)
    fc4_kernel<<<32, 128>>>(b4, out);                // 4096
}

// round 8
// speedup vs baseline: 1.2417x; 1.0018x over previous
#include <cuda_runtime.h>

#define BATCH 4096

// ---------------- Device scratch ----------------
__device__ unsigned g_w1p[20];                         // 25 sign bits per filter
__device__ __align__(16) unsigned g_w2q[50*16];        // per filter: 500-bit window layout (p = t*20+c)
__device__ __align__(16) unsigned g_w3p[1024*80];      // per out-neuron: 2450 bits, order j' = pix*50+c, pad 80
__device__ unsigned g_w4p[10*32];                      // per out-neuron: 1024 sign bits
__device__ unsigned g_xrow[BATCH*64];                  // per image: [0..31]=mask rows, [32..63]=sign rows (bit xx+2)
__device__ unsigned g_packed1[BATCH*324];              // conv2 input: padded 18x18, 20 ch bits per pixel
__device__ __align__(16) unsigned g_packed2[BATCH*80]; // fc3 input bits (order pix*50+c), padded
__device__ unsigned g_packed3[BATCH*32];               // fc4 input bits (1024)

// ---------------- Weight packing ----------------
// ranges: [0,20) w1 | [20,820) w2q | [820,82740) w3 | [82740,83060) w4
__global__ void pack_w_kernel(const float* __restrict__ w1, const float* __restrict__ w2,
                              const float* __restrict__ w3, const float* __restrict__ w4) {
    int id = blockIdx.x * blockDim.x + threadIdx.x;
    if (id < 20) {
        unsigned m = 0;
        #pragma unroll
        for (int t = 0; t < 25; t++) m |= (unsigned)(w1[id*25 + t] > 0.0f) << t;
        g_w1p[id] = m;
    } else if (id < 820) {
        int idx = id - 20; int f = idx / 16, w = idx % 16;
        unsigned m = 0;
        for (int k = 0; k < 32; k++) {
            int p = w*32 + k;
            if (p < 500) {
                int t = p / 20, c = p % 20;
                m |= (unsigned)(w2[f*500 + c*25 + t] > 0.0f) << k;
            }
        }
        g_w2q[idx] = m;
    } else if (id < 82740) {
        int idx = id - 820; int o = idx / 80, w = idx % 80;
        unsigned m = 0;
        for (int k = 0; k < 32; k++) {
            int j = w*32 + k;
            if (j < 2450) {
                int pix = j / 50, c = j % 50;  // orig flat index = c*49 + pix
                m |= (unsigned)(w3[o*2450 + c*49 + pix] > 0.0f) << k;
            }
        }
        g_w3p[idx] = m;
    } else if (id < 83060) {
        int idx = id - 82740; int o = idx / 32, w = idx % 32;
        unsigned m = 0;
        #pragma unroll
        for (int k = 0; k < 32; k++) m |= (unsigned)(w4[o*1024 + w*32 + k] > 0.0f) << k;
        g_w4p[idx] = m;
    }
}

// ---------------- pack x into per-row mask/sign bit words ----------------
__global__ void pack_xrow_kernel(const float* __restrict__ x) {
    int id = blockIdx.x * 128 + threadIdx.x;          // 1024*128 = 4096*32
    int b = id >> 5, r = id & 31;
    unsigned m = 0, p = 0;
    if (r >= 2 && r < 30) {
        const float* row = x + b*784 + (r-2)*28;
        #pragma unroll
        for (int xx = 0; xx < 28; xx++) {
            float v = row[xx];
            m |= (unsigned)(v != 0.0f) << (xx + 2);
            p |= (unsigned)(v > 0.0f)  << (xx + 2);
        }
    }
    g_xrow[b*64 + r]      = m;
    g_xrow[b*64 + 32 + r] = p;
}

// ---------------- conv1 + relu + maxpool2 + sign -> padded 18x18 channel-bit words ----------------
__global__ void __launch_bounds__(128) conv1_kernel(const float* __restrict__ b1) {
    __shared__ unsigned w1s[20];
    __shared__ float b1s[20];
    int tid = threadIdx.x;
    if (tid < 20) { w1s[tid] = g_w1p[tid]; b1s[tid] = b1[tid]; }
    __syncthreads();

    int id = blockIdx.x * 128 + tid;                 // 6272*128 = 4096*196
    if (id < BATCH*80) g_packed2[id] = 0;            // zero fc3-input rows for conv2's atomicOr
    int b = id / 196, pix = id % 196;
    int py = pix / 14, px = pix % 14;
    unsigned* p1b = g_packed1 + b * 324;

    // zero the 128 border cells of the 18x18 padded image
    if (pix < 128) {
        int y, xx;
        if (pix < 72) { int ry = pix / 18; y = (ry < 2) ? ry : ry + 14; xx = pix % 18; }
        else { int j = pix - 72; int cx = j % 4; xx = (cx < 2) ? cx : cx + 14; y = 2 + j / 4; }
        p1b[y*18 + xx] = 0u;
    }

    const unsigned* xr = g_xrow + b*64;
    unsigned mr[6], pr[6];
    #pragma unroll
    for (int i = 0; i < 6; i++) { mr[i] = xr[2*py + i]; pr[i] = xr[32 + 2*py + i]; }

    unsigned M[4], P[4]; int pm[4];
    #pragma unroll
    for (int dy = 0; dy < 2; dy++)
    #pragma unroll
    for (int dx = 0; dx < 2; dx++) {
        int sh = 2*px + dx;
        unsigned m = 0, p = 0;
        #pragma unroll
        for (int ky = 0; ky < 5; ky++) {
            m |= ((mr[dy + ky] >> sh) & 31u) << (5*ky);
            p |= ((pr[dy + ky] >> sh) & 31u) << (5*ky);
        }
        int w = dy*2 + dx;
        M[w] = m; P[w] = p; pm[w] = __popc(m);
    }

    unsigned word = 0;
    #pragma unroll
    for (int c = 0; c < 20; c++) {
        unsigned wp = w1s[c];
        int d0 = 2*__popc(M[0] & ~(P[0] ^ wp)) - pm[0];
        int d1 = 2*__popc(M[1] & ~(P[1] ^ wp)) - pm[1];
        int d2 = 2*__popc(M[2] & ~(P[2] ^ wp)) - pm[2];
        int d3 = 2*__popc(M[3] & ~(P[3] ^ wp)) - pm[3];
        int mx = max(max(d0, d1), max(d2, d3));
        if ((float)mx + b1s[c] > 0.0f) word |= 1u << c;
    }
    p1b[(py + 2)*18 + (px + 2)] = word;
}

// ---------------- conv2: 4 sequential windows, single W[16], padded loads ----------------
__global__ void __launch_bounds__(128, 8) conv2_kernel(const float* __restrict__ b2) {
    __shared__ __align__(16) unsigned sw[50*16];
    __shared__ int thr[50];
    int tid = threadIdx.x;
    for (int t = tid; t < 800; t += 128) sw[t] = g_w2q[t];
    // (float)d + bias > 0  <=>  d >= floor(-bias)+1   (d integer)
    if (tid < 50) thr[tid] = (int)floorf(-b2[tid]) + 1;
    __syncthreads();

    int id = blockIdx.x * 128 + tid;                 // 1568*128 = 4096*49
    int b = id / 49, pix = id % 49;
    int py = pix / 7, px = pix % 7;
    const unsigned* inb = g_packed1 + b * 324;

    unsigned long long bits = 0ull;

    #pragma unroll 1
    for (int win = 0; win < 4; win++) {
        // window top-left in padded coords: (py*2 + dy, px*2 + dx); pad offset folds away
        const unsigned* base = inb + (py*2 + (win >> 1))*18 + (px*2 + (win & 1));

        unsigned W[16];
        {
            unsigned long long acc = 0; int off = 0, wi = 0;
            #pragma unroll
            for (int ky = 0; ky < 5; ky++)
            #pragma unroll
            for (int kx = 0; kx < 5; kx++) {
                unsigned long long v = base[ky*18 + kx];
                acc |= v << off;
                off += 20;
                if (off >= 32) { W[wi++] = (unsigned)acc; acc >>= 32; off -= 32; }
            }
            W[wi] = (unsigned)acc;
        }

        int S = 0;
        #pragma unroll
        for (int j = 0; j < 16; j++) S += __popc(W[j]);

        #pragma unroll 2
        for (int f = 0; f < 50; f++) {
            const uint4* fp = (const uint4*)&sw[f*16];
            int P = 0;
            #pragma unroll
            for (int q = 0; q < 4; q++) {
                uint4 w = fp[q];
                P += __popc(W[q*4+0] & w.x) + __popc(W[q*4+1] & w.y)
                   + __popc(W[q*4+2] & w.z) + __popc(W[q*4+3] & w.w);
            }
            bits |= (unsigned long long)(2*P - S >= thr[f]) << f;
        }
    }

    // scatter 50 bits into the fc3 bit row at offset pix*50
    unsigned* row = g_packed2 + b * 80;
    int base = pix * 50;
    int w0 = base >> 5, sh = base & 31;
    unsigned long long lo = bits << sh;
    atomicOr(&row[w0],     (unsigned)lo);
    atomicOr(&row[w0 + 1], (unsigned)(lo >> 32));
    if (sh >= 15) atomicOr(&row[w0 + 2], (unsigned)(bits >> (64 - sh)));
}

// ---------------- fc3: register-tiled 4 outputs x 8 batches per thread ----------------
__global__ void __launch_bounds__(128) fc3_kernel(const float* __restrict__ b3) {
    __shared__ __align__(16) unsigned sa[8*80];
    __shared__ int sna[8];
    int tid = threadIdx.x;
    int b0 = blockIdx.y * 8;
    for (int t = tid; t < 160; t += 128)
        ((uint4*)sa)[t] = ((const uint4*)(g_packed2 + b0*80))[t];
    __syncthreads();
    if (tid < 8) {
        int s = 0;
        #pragma unroll 8
        for (int i = 0; i < 80; i++) s += __popc(sa[tid*80 + i]);
        sna[tid] = s;
    }
    __syncthreads();

    int obase = blockIdx.x * 512 + tid;              // outputs obase + 128*j, j=0..3
    const uint4* wr0 = (const uint4*)(g_w3p + (obase      )*80);
    const uint4* wr1 = (const uint4*)(g_w3p + (obase + 128)*80);
    const uint4* wr2 = (const uint4*)(g_w3p + (obase + 256)*80);
    const uint4* wr3 = (const uint4*)(g_w3p + (obase + 384)*80);

    int cnt[4][8];
    #pragma unroll
    for (int j = 0; j < 4; j++)
        #pragma unroll
        for (int bb = 0; bb < 8; bb++) cnt[j][bb] = 0;

    #pragma unroll 2
    for (int i = 0; i < 20; i++) {
        uint4 w[4] = {wr0[i], wr1[i], wr2[i], wr3[i]};
        #pragma unroll
        for (int bb = 0; bb < 8; bb++) {
            uint4 a = *(const uint4*)&sa[bb*80 + i*4];
            #pragma unroll
            for (int j = 0; j < 4; j++) {
                cnt[j][bb] += __popc(a.x & w[j].x) + __popc(a.y & w[j].y)
                            + __popc(a.z & w[j].z) + __popc(a.w & w[j].w);
            }
        }
    }

    #pragma unroll
    for (int j = 0; j < 4; j++) {
        int o = obase + 128*j;
        float bias = b3[o];
        int widx = o >> 5;
        #pragma unroll
        for (int bb = 0; bb < 8; bb++) {
            float val = (float)(2*cnt[j][bb] - sna[bb]) + bias;
            unsigned word = __ballot_sync(0xffffffffu, val > 0.0f);
            if ((tid & 31) == 0) g_packed3[(b0 + bb)*32 + widx] = word;
        }
    }
}

// ---------------- fc4: [4096,1024] x [10,1024]^T -> float out ----------------
__global__ void __launch_bounds__(128) fc4_kernel(const float* __restrict__ b4, float* __restrict__ out) {
    __shared__ unsigned w4s[10*32];
    __shared__ float b4s[10];
    int tid = threadIdx.x;
    for (int t = tid; t < 320; t += 128) w4s[t] = g_w4p[t];
    if (tid < 10) b4s[tid] = b4[tid];
    __syncthreads();

    int b = blockIdx.x * 128 + tid;                  // 32*128 = 4096
    unsigned a[32]; int na = 0;
    #pragma unroll
    for (int i = 0; i < 32; i++) { a[i] = g_packed3[b*32 + i]; na += __popc(a[i]); }
    #pragma unroll
    for (int k = 0; k < 10; k++) {
        int cnt = 0;
        #pragma unroll
        for (int i = 0; i < 32; i++) cnt += __popc(a[i] & w4s[k*32 + i]);
        out[b*10 + k] = (float)(2*cnt - na) + b4s[k];
    }
}

// ---------------- launch ----------------
extern "C" void kernel_launch(void* const* d_in, const int* in_sizes, int n_in,
                              void* d_out, int out_size) {
    const float* x  = (const float*)d_in[0];
    const float* w1 = (const float*)d_in[1];
    const float* b1 = (const float*)d_in[2];
    const float* w2 = (const float*)d_in[3];
    const float* b2 = (const float*)d_in[4];
    const float* w3 = (const float*)d_in[5];
    const float* b3 = (const float*)d_in[6];
    const float* w4 = (const float*)d_in[7];
    const float* b4 = (const float*)d_in[8];
    float* out = (float*)d_out;

    pack_w_kernel<<<649, 128>>>(w1, w2, w3, w4);     // 83060 items
    pack_xrow_kernel<<<1024, 128>>>(x);              // 4096*32 rows
    conv1_kernel<<<6272, 128>>>(b1);                 // 4096*196 (+ zeroes g_packed2, borders)
    conv2_kernel<<<1568, 128>>>(b2);                 // 4096*49
    fc3_kernel<<<dim3(2, 512), 128>>>(b3);           // 1024 outs x (4096/8)
    fc4_kernel<<<32, 128>>>(b4, out);                // 4096
}